// round 11
// baseline (speedup 1.0000x reference)
#include <cuda_runtime.h>
#include <cuda_bf16.h>

// Problem constants
#define BB 2
#define NN 8192
#define HALF_N 4096
#define CC 64
#define DD 3
#define MM 2048   // NPOINT
#define SS 32     // NSAMPLE

// Output layout (concatenated tuple, row-major each)
#define OFF_GXYZ 0L
#define OFF_GFTS 393216L
#define OFF_NXYZ (393216L + 50331648L)
#define OFF_NFTS (393216L + 50331648L + 12288L)

__device__ int g_fps[BB * MM];
__device__ int g_nbr[BB * MM * SS];

// packed f32x2 helpers (lane-wise IEEE rn — bit-identical to scalar)
#define MUL_F32X2(out, a, b) \
    asm("mul.rn.f32x2 %0, %1, %2;" : "=l"(out) : "l"(a), "l"(b))
#define ADD_F32X2(out, a, b) \
    asm("add.rn.f32x2 %0, %1, %2;" : "=l"(out) : "l"(a), "l"(b))
#define PACK_F32X2(out, lo, hi) \
    asm("mov.b64 %0, {%1, %2};" : "=l"(out) : "f"(lo), "f"(hi))
#define UNPACK_F32X2(lo, hi, in) \
    asm("mov.b64 {%0, %1}, %2;" : "=f"(lo), "=f"(hi) : "l"(in))

__device__ __forceinline__ unsigned redux_max_u32(unsigned v) {
    unsigned r;
    asm volatile("redux.sync.max.u32 %0, %1, 0xffffffff;" : "=r"(r) : "r"(v));
    return r;
}

__device__ __forceinline__ unsigned smem_u32(const void* p) {
    unsigned a;
    asm("{ .reg .u64 t; cvta.to.shared.u64 t, %1; cvt.u32.u64 %0, t; }"
        : "=r"(a) : "l"(p));
    return a;
}

#define MBARRIER_INIT_(addr, cnt) \
    asm volatile("mbarrier.init.shared.b64 [%0], %1;" :: "r"(addr), "r"(cnt) : "memory")

// acquire at CLUSTER scope — makes peer's shared::cluster store visible
#define MBAR_WAIT_CL(mbar, ph) do {                                            \
    unsigned _p;                                                               \
    asm volatile("{\n\t.reg .pred P;\n\t"                                      \
        "mbarrier.try_wait.parity.acquire.cluster.shared::cta.b64 P, [%1], %2;\n\t" \
        "selp.b32 %0, 1, 0, P;\n\t}"                                           \
        : "=r"(_p) : "r"(mbar), "r"(ph) : "memory");                           \
    if (!_p) {                                                                 \
        asm volatile("{\n\t.reg .pred P;\n\t"                                  \
            "WL_%=:\n\t"                                                       \
            "mbarrier.try_wait.parity.acquire.cluster.shared::cta.b64 P, [%0], %1;\n\t" \
            "@P bra.uni WD_%=;\n\t"                                            \
            "bra.uni WL_%=;\n\t"                                               \
            "WD_%=:\n\t}"                                                      \
            :: "r"(mbar), "r"(ph) : "memory");                                 \
    }                                                                          \
} while (0)

#define CLUSTER_SYNC_() do {                                      \
    asm volatile("barrier.cluster.arrive.aligned;" ::: "memory"); \
    asm volatile("barrier.cluster.wait.aligned;" ::: "memory");   \
} while (0)

// strict (non-contracted) square-sum — matches reference fused square+reduce
__device__ __forceinline__ float sq3(float x, float y, float z) {
    return __fadd_rn(__fadd_rn(__fmul_rn(x, x), __fmul_rn(y, y)), __fmul_rn(z, z));
}

// ---------------------------------------------------------------------------
// 1) FPS: 2-CTA cluster per batch; each CTA: 256 threads x 16 points (4096).
//    Packed-f32x2 strict distances; value-only min/max inner loop;
//    redux.sync warp max; ffs index recovery; cross-CTA combine via DSMEM
//    key exchange (key = (maxbits<<32)|~idx → max-key == first-index argmax).
// ---------------------------------------------------------------------------
__global__ void __cluster_dims__(2, 1, 1) __launch_bounds__(256, 1)
fps_kernel(const float* __restrict__ xyz) {
    const int b = blockIdx.y;
    unsigned rank;
    asm("mov.u32 %0, %%cluster_ctarank;" : "=r"(rank));
    const float* p = xyz + (long)b * NN * 3;
    const int tid = threadIdx.x;
    const int lane = tid & 31, warp = tid >> 5;
    const int base = rank * HALF_N;

    // point i = base + j*256 + tid, j in [0,16); pairs (2k, 2k+1)
    unsigned long long px2[8], py2[8], pz2[8];
    float md[16];
#pragma unroll
    for (int k = 0; k < 8; k++) {
        int i0 = base + (2 * k) * 256 + tid;
        int i1 = base + (2 * k + 1) * 256 + tid;
        PACK_F32X2(px2[k], p[3 * i0 + 0], p[3 * i1 + 0]);
        PACK_F32X2(py2[k], p[3 * i0 + 1], p[3 * i1 + 1]);
        PACK_F32X2(pz2[k], p[3 * i0 + 2], p[3 * i1 + 2]);
        md[2 * k] = 1e10f;
        md[2 * k + 1] = 1e10f;
    }

    __shared__ unsigned            s_val[8];
    __shared__ int                 s_idx[2];
    __shared__ unsigned long long  s_peer[2];
    __shared__ unsigned long long  s_mbar;

    const unsigned mbar_a  = smem_u32(&s_mbar);
    const unsigned peer_a0 = smem_u32(&s_peer[0]);

    if (tid == 0) {
        if (rank == 0) g_fps[b * MM] = 0;
        s_idx[0] = 0x7fffffff;
        s_idx[1] = 0x7fffffff;
        MBARRIER_INIT_(mbar_a, 1);
    }
    __syncthreads();
    CLUSTER_SYNC_();   // peer's mbarrier init visible before any remote arrive

    float lx = p[0], ly = p[1], lz = p[2];

    for (int it = 1; it < MM; it++) {
        unsigned long long nlx2, nly2, nlz2;
        float nlx = -lx, nly = -ly, nlz = -lz;
        PACK_F32X2(nlx2, nlx, nlx);
        PACK_F32X2(nly2, nly, nly);
        PACK_F32X2(nlz2, nlz, nlz);

        float bv = -1.0f;
#pragma unroll
        for (int k = 0; k < 8; k++) {
            unsigned long long dx2, dy2, dz2, xx, yy, ss, zz, dd;
            ADD_F32X2(dx2, px2[k], nlx2);           // x - lx  (== x + (-lx))
            ADD_F32X2(dy2, py2[k], nly2);
            ADD_F32X2(dz2, pz2[k], nlz2);
            MUL_F32X2(xx, dx2, dx2);
            MUL_F32X2(yy, dy2, dy2);
            ADD_F32X2(ss, xx, yy);                  // (dx² + dy²)
            MUL_F32X2(zz, dz2, dz2);
            ADD_F32X2(dd, ss, zz);                  // + dz²
            float dlo, dhi;
            UNPACK_F32X2(dlo, dhi, dd);
            float m0 = fminf(md[2 * k], dlo);
            float m1 = fminf(md[2 * k + 1], dhi);
            md[2 * k] = m0;
            md[2 * k + 1] = m1;
            bv = fmaxf(bv, m0);
            bv = fmaxf(bv, m1);
        }

        // warp max via redux (distances non-negative → u32 order == f32 order)
        const unsigned ub = __float_as_uint(bv);
        const unsigned wmax = redux_max_u32(ub);
        if (lane == 0) s_val[warp] = wmax;
        __syncthreads();                            // bar A

        unsigned bm = s_val[0];
#pragma unroll
        for (int k = 1; k < 8; k++) bm = bm > s_val[k] ? bm : s_val[k];

        const int slot = it & 1;
        if (ub == bm) {
            // lowest j with md[j] == blockmax → first (lowest) index for this thread
            const float bmf = __uint_as_float(bm);
            unsigned mask = 0;
#pragma unroll
            for (int j = 0; j < 16; j++)
                if (md[j] == bmf) mask |= (1u << j);
            int jmin = __ffs(mask) - 1;
            atomicMin(&s_idx[slot], base + jmin * 256 + tid);
        }
        if (tid == 0) s_idx[slot ^ 1] = 0x7fffffff;  // reset next slot
        __syncthreads();                            // bar B

        const unsigned long long okey =
            ((unsigned long long)bm << 32) | (unsigned)(~s_idx[slot]);

        if (tid == 0) {
            unsigned rdata, rbar;
            const unsigned pa = peer_a0 + slot * 8;
            asm("mapa.shared::cluster.u32 %0, %1, %2;" : "=r"(rdata) : "r"(pa), "r"(rank ^ 1));
            asm volatile("st.shared::cluster.u64 [%0], %1;" :: "r"(rdata), "l"(okey) : "memory");
            asm("mapa.shared::cluster.u32 %0, %1, %2;" : "=r"(rbar) : "r"(mbar_a), "r"(rank ^ 1));
            // release orders the store above at cluster scope before the arrive
            asm volatile("mbarrier.arrive.release.cluster.shared::cluster.b64 _, [%0];"
                         :: "r"(rbar) : "memory");
        }

        MBAR_WAIT_CL(mbar_a, (it - 1) & 1);          // peer key arrived
        const unsigned long long pkey = s_peer[slot];
        const unsigned long long fk = okey > pkey ? okey : pkey;
        const int last = (int)(~(unsigned)fk);

        if (rank == 0 && tid == 0) g_fps[b * MM + it] = last;
        lx = p[3 * last + 0];                        // L1 broadcast
        ly = p[3 * last + 1];
        lz = p[3 * last + 2];
    }

    CLUSTER_SYNC_();   // don't tear down smem while peer may still access it
}

// ---------------------------------------------------------------------------
// 2) KNN (v10 — verified exact): qq/pp strict; dot fma-ascending;
//    d = qq + (pp - 2*dot); ties lower-index-first.
// ---------------------------------------------------------------------------
__global__ void __launch_bounds__(256) knn_kernel(const float* __restrict__ xyz) {
    const int m = blockIdx.x;
    const int b = blockIdx.y;
    const float* p = xyz + (long)b * NN * 3;
    const int t = threadIdx.x;

    const int qi = g_fps[b * MM + m];
    const float qx = p[3 * qi + 0], qy = p[3 * qi + 1], qz = p[3 * qi + 2];
    const float qq = sq3(qx, qy, qz);

    float d[32];
#pragma unroll
    for (int j = 0; j < 32; j++) {
        int i = j * 256 + t;
        float x = p[3 * i + 0], y = p[3 * i + 1], z = p[3 * i + 2];
        float pp = sq3(x, y, z);
        float dot = __fmaf_rn(qz, z, __fmaf_rn(qy, y, __fmul_rn(qx, x)));
        d[j] = __fadd_rn(qq, __fsub_rn(pp, __fmul_rn(2.0f, dot)));
    }

    unsigned excl = 0u;
    float mv = d[0];
    int mi = t;
#pragma unroll
    for (int j = 1; j < 32; j++) {
        int i = j * 256 + t;
        if (d[j] < mv) { mv = d[j]; mi = i; }  // strict < : lower idx wins ties
    }

    __shared__ float s_v[8];
    __shared__ int   s_i[8];
    __shared__ int   s_b;
    const int lane = t & 31, w = t >> 5;
    const int out_base = (b * MM + m) * SS;

    for (int s = 0; s < SS; s++) {
        float bv = mv;
        int bi = mi;
#pragma unroll
        for (int o = 16; o > 0; o >>= 1) {
            float ov = __shfl_down_sync(0xffffffffu, bv, o);
            int   oi = __shfl_down_sync(0xffffffffu, bi, o);
            if (ov < bv || (ov == bv && oi < bi)) { bv = ov; bi = oi; }
        }
        if (lane == 0) { s_v[w] = bv; s_i[w] = bi; }
        __syncthreads();
        if (t == 0) {
            bv = s_v[0]; bi = s_i[0];
#pragma unroll
            for (int k = 1; k < 8; k++) {
                float ov = s_v[k]; int oi = s_i[k];
                if (ov < bv || (ov == bv && oi < bi)) { bv = ov; bi = oi; }
            }
            s_b = bi;
            g_nbr[out_base + s] = bi;
        }
        __syncthreads();
        int win = s_b;
        if ((win & 255) == t) {
            excl |= 1u << (win >> 8);
            mv = 3.4e38f;
            mi = 0x7fffffff;
#pragma unroll
            for (int j = 0; j < 32; j++) {
                if (!(excl & (1u << j))) {
                    int i = j * 256 + t;
                    if (d[j] < mv) { mv = d[j]; mi = i; }
                }
            }
        }
    }
}

// ---------------------------------------------------------------------------
// 3) group_xyz + new_xyz
// ---------------------------------------------------------------------------
__global__ void __launch_bounds__(256) gxyz_kernel(const float* __restrict__ xyz,
                                                   float* __restrict__ out) {
    int tid = blockIdx.x * 256 + threadIdx.x;
    if (tid >= BB * MM * SS) return;
    int s = tid & 31;
    int m = (tid >> 5) & (MM - 1);
    int b = tid >> 16;
    const float* p = xyz + (long)b * NN * 3;

    int i = g_nbr[tid];
    float* o = out + OFF_GXYZ + (long)tid * 3;
    o[0] = p[3 * i + 0];
    o[1] = p[3 * i + 1];
    o[2] = p[3 * i + 2];

    if (s == 0) {
        int q = g_fps[b * MM + m];
        float* o2 = out + OFF_NXYZ + (long)(b * MM + m) * 3;
        o2[0] = p[3 * q + 0];
        o2[1] = p[3 * q + 1];
        o2[2] = p[3 * q + 2];
    }
}

// ---------------------------------------------------------------------------
// 4) group_fts + new_fts_out
// ---------------------------------------------------------------------------
__global__ void __launch_bounds__(256) gfts_kernel(const float* __restrict__ fts,
                                                   float* __restrict__ out) {
    __shared__ float row[NN];
    __shared__ float ctr[512];

    const int r = blockIdx.x;       // 0..383
    const int chunk = blockIdx.y;   // 0..3
    const int b = r / (CC * DD);
    const int cd = r % (CC * DD);
    const int c = cd / DD;
    const int dd = cd % DD;
    const int t = threadIdx.x;

    const float* src = fts + ((long)(b * CC + c) * DD + dd) * NN;
#pragma unroll
    for (int k = 0; k < 8; k++) {
        int i = (k * 256 + t) * 4;
        *(float4*)&row[i] = *(const float4*)&src[i];
    }
    __syncthreads();

    const int m0 = chunk * 512;
#pragma unroll
    for (int k = 0; k < 2; k++) {
        int ml = k * 256 + t;
        ctr[ml] = row[g_fps[b * MM + m0 + ml]];
    }
    __syncthreads();

    float* o1 = out + OFF_GFTS + ((long)(b * 2 * CC + c) * DD + dd) * MM * SS;
    float* o2 = o1 + (long)CC * DD * MM * SS;
    const int* nb = g_nbr + (b * MM + m0) * SS;
    float* nfo1 = out + OFF_NFTS + ((long)(b * 2 * CC + c) * DD + dd) * MM + m0;
    float* nfo2 = nfo1 + (long)CC * DD * MM;

    for (int e = t; e < 512 * 8; e += 256) {
        int ml = e >> 3;
        int s4 = e & 7;
        int m = m0 + ml;
        int4 idx = *(const int4*)&nb[ml * SS + s4 * 4];
        float cv = ctr[ml];
        float4 v;
        v.x = __fsub_rn(row[idx.x], cv);
        v.y = __fsub_rn(row[idx.y], cv);
        v.z = __fsub_rn(row[idx.z], cv);
        v.w = __fsub_rn(row[idx.w], cv);
        long oo = (long)m * SS + s4 * 4;
        *(float4*)&o1[oo] = v;
        float4 cc4 = {cv, cv, cv, cv};
        *(float4*)&o2[oo] = cc4;
        if (s4 == 0) {
            nfo1[ml] = v.x;
            nfo2[ml] = cv;
        }
    }
}

// ---------------------------------------------------------------------------
extern "C" void kernel_launch(void* const* d_in, const int* in_sizes, int n_in,
                              void* d_out, int out_size) {
    const float* xyz = (const float*)d_in[0];
    const float* fts = (const float*)d_in[1];
    if (n_in >= 2 && in_sizes[0] != BB * NN * 3) {
        const float* tmp = xyz; xyz = fts; fts = tmp;
    }
    float* out = (float*)d_out;

    dim3 fg(2, BB);                    // 2-CTA cluster per batch
    fps_kernel<<<fg, 256>>>(xyz);

    dim3 kg(MM, BB);
    knn_kernel<<<kg, 256>>>(xyz);

    gxyz_kernel<<<(BB * MM * SS + 255) / 256, 256>>>(xyz, out);

    dim3 gg(BB * CC * DD, 4);
    gfts_kernel<<<gg, 256>>>(fts, out);
}

// round 12
// speedup vs baseline: 1.3301x; 1.3301x over previous
#include <cuda_runtime.h>
#include <cuda_bf16.h>

// Problem constants
#define BB 2
#define NN 8192
#define CC 64
#define DD 3
#define MM 2048   // NPOINT
#define SS 32     // NSAMPLE

// Output layout (concatenated tuple, row-major each)
#define OFF_GXYZ 0L
#define OFF_GFTS 393216L
#define OFF_NXYZ (393216L + 50331648L)
#define OFF_NFTS (393216L + 50331648L + 12288L)

__device__ int g_fps[BB * MM];
__device__ int g_nbr[BB * MM * SS];

// packed f32x2 helpers (lane-wise IEEE rn — bit-identical to scalar)
#define MUL_F32X2(out, a, b) \
    asm("mul.rn.f32x2 %0, %1, %2;" : "=l"(out) : "l"(a), "l"(b))
#define ADD_F32X2(out, a, b) \
    asm("add.rn.f32x2 %0, %1, %2;" : "=l"(out) : "l"(a), "l"(b))
#define PACK_F32X2(out, lo, hi) \
    asm("mov.b64 %0, {%1, %2};" : "=l"(out) : "f"(lo), "f"(hi))
#define UNPACK_F32X2(lo, hi, in) \
    asm("mov.b64 {%0, %1}, %2;" : "=f"(lo), "=f"(hi) : "l"(in))

__device__ __forceinline__ unsigned redux_max_u32(unsigned v) {
    unsigned r;
    asm volatile("redux.sync.max.u32 %0, %1, 0xffffffff;" : "=r"(r) : "r"(v));
    return r;
}

// strict (non-contracted) square-sum — matches reference fused square+reduce
__device__ __forceinline__ float sq3(float x, float y, float z) {
    return __fadd_rn(__fadd_rn(__fmul_rn(x, x), __fmul_rn(y, y)), __fmul_rn(z, z));
}

// ---------------------------------------------------------------------------
// 1) FPS: one block/batch, 256 threads x 32 pts. Packed-f32x2 strict
//    distances; value-only min/max inner loop; tail = warp redux +
//    single u64 atomicMax key + ONE barrier per iteration.
//    key = (maxbits<<32) | ~idx  →  max key == first-index argmax
//    (distances >= 0 so u32 order == f32 order; ~idx: ties -> lowest idx).
// ---------------------------------------------------------------------------
__global__ void __launch_bounds__(256, 1) fps_kernel(const float* __restrict__ xyz) {
    const int b = blockIdx.x;
    const float* p = xyz + (long)b * NN * 3;
    const int tid = threadIdx.x;

    // point i = j*256 + tid, j in [0,32); pairs (2k, 2k+1)
    unsigned long long px2[16], py2[16], pz2[16];
    float md[32];
#pragma unroll
    for (int k = 0; k < 16; k++) {
        int i0 = (2 * k) * 256 + tid;
        int i1 = (2 * k + 1) * 256 + tid;
        PACK_F32X2(px2[k], p[3 * i0 + 0], p[3 * i1 + 0]);
        PACK_F32X2(py2[k], p[3 * i0 + 1], p[3 * i1 + 1]);
        PACK_F32X2(pz2[k], p[3 * i0 + 2], p[3 * i1 + 2]);
        md[2 * k] = 1e10f;
        md[2 * k + 1] = 1e10f;
    }

    __shared__ unsigned long long s_key[2];

    if (tid == 0) {
        g_fps[b * MM] = 0;
        s_key[0] = 0ULL;
        s_key[1] = 0ULL;
    }
    __syncthreads();

    float lx = p[0], ly = p[1], lz = p[2];

    for (int it = 1; it < MM; it++) {
        unsigned long long nlx2, nly2, nlz2;
        float nlx = -lx, nly = -ly, nlz = -lz;
        PACK_F32X2(nlx2, nlx, nlx);
        PACK_F32X2(nly2, nly, nly);
        PACK_F32X2(nlz2, nlz, nlz);

        float bv = -1.0f;
#pragma unroll
        for (int k = 0; k < 16; k++) {
            unsigned long long dx2, dy2, dz2, xx, yy, ss, zz, dd;
            ADD_F32X2(dx2, px2[k], nlx2);           // x - lx  (== x + (-lx))
            ADD_F32X2(dy2, py2[k], nly2);
            ADD_F32X2(dz2, pz2[k], nlz2);
            MUL_F32X2(xx, dx2, dx2);
            MUL_F32X2(yy, dy2, dy2);
            ADD_F32X2(ss, xx, yy);                  // (dx² + dy²)
            MUL_F32X2(zz, dz2, dz2);
            ADD_F32X2(dd, ss, zz);                  // + dz²
            float dlo, dhi;
            UNPACK_F32X2(dlo, dhi, dd);
            float m0 = fminf(md[2 * k], dlo);
            float m1 = fminf(md[2 * k + 1], dhi);
            md[2 * k] = m0;
            md[2 * k + 1] = m1;
            bv = fmaxf(bv, m0);
            bv = fmaxf(bv, m1);
        }

        // warp max (distances non-negative → u32 order == f32 order)
        const unsigned ub = __float_as_uint(bv);
        const unsigned wmax = redux_max_u32(ub);
        const int slot = it & 1;

        if (ub == wmax) {
            // this thread holds its warp's max; find its FIRST (lowest) index
            const float bmf = __uint_as_float(wmax);
            unsigned lo = 0, hi = 0;
#pragma unroll
            for (int j = 0; j < 16; j++) {
                if (md[j] == bmf)      lo |= (1u << j);
                if (md[j + 16] == bmf) hi |= (1u << j);
            }
            int jmin = lo ? (__ffs(lo) - 1) : (__ffs(hi) + 15);
            unsigned long long key =
                ((unsigned long long)wmax << 32) | (unsigned)~(jmin * 256 + tid);
            atomicMax(&s_key[slot], key);
        }
        if (tid == 0) s_key[slot ^ 1] = 0ULL;        // reset next slot (pre-bar)
        __syncthreads();                             // single barrier per iter

        const int last = (int)(~(unsigned)s_key[slot]);
        if (tid == 0) g_fps[b * MM + it] = last;
        lx = p[3 * last + 0];                        // L1 broadcast
        ly = p[3 * last + 1];
        lz = p[3 * last + 2];
    }
}

// ---------------------------------------------------------------------------
// 2) KNN (v10 — verified exact): qq/pp strict; dot fma-ascending;
//    d = qq + (pp - 2*dot); ties lower-index-first.
// ---------------------------------------------------------------------------
__global__ void __launch_bounds__(256) knn_kernel(const float* __restrict__ xyz) {
    const int m = blockIdx.x;
    const int b = blockIdx.y;
    const float* p = xyz + (long)b * NN * 3;
    const int t = threadIdx.x;

    const int qi = g_fps[b * MM + m];
    const float qx = p[3 * qi + 0], qy = p[3 * qi + 1], qz = p[3 * qi + 2];
    const float qq = sq3(qx, qy, qz);

    float d[32];
#pragma unroll
    for (int j = 0; j < 32; j++) {
        int i = j * 256 + t;
        float x = p[3 * i + 0], y = p[3 * i + 1], z = p[3 * i + 2];
        float pp = sq3(x, y, z);
        float dot = __fmaf_rn(qz, z, __fmaf_rn(qy, y, __fmul_rn(qx, x)));
        d[j] = __fadd_rn(qq, __fsub_rn(pp, __fmul_rn(2.0f, dot)));
    }

    unsigned excl = 0u;
    float mv = d[0];
    int mi = t;
#pragma unroll
    for (int j = 1; j < 32; j++) {
        int i = j * 256 + t;
        if (d[j] < mv) { mv = d[j]; mi = i; }  // strict < : lower idx wins ties
    }

    __shared__ float s_v[8];
    __shared__ int   s_i[8];
    __shared__ int   s_b;
    const int lane = t & 31, w = t >> 5;
    const int out_base = (b * MM + m) * SS;

    for (int s = 0; s < SS; s++) {
        float bv = mv;
        int bi = mi;
#pragma unroll
        for (int o = 16; o > 0; o >>= 1) {
            float ov = __shfl_down_sync(0xffffffffu, bv, o);
            int   oi = __shfl_down_sync(0xffffffffu, bi, o);
            if (ov < bv || (ov == bv && oi < bi)) { bv = ov; bi = oi; }
        }
        if (lane == 0) { s_v[w] = bv; s_i[w] = bi; }
        __syncthreads();
        if (t == 0) {
            bv = s_v[0]; bi = s_i[0];
#pragma unroll
            for (int k = 1; k < 8; k++) {
                float ov = s_v[k]; int oi = s_i[k];
                if (ov < bv || (ov == bv && oi < bi)) { bv = ov; bi = oi; }
            }
            s_b = bi;
            g_nbr[out_base + s] = bi;
        }
        __syncthreads();
        int win = s_b;
        if ((win & 255) == t) {
            excl |= 1u << (win >> 8);
            mv = 3.4e38f;
            mi = 0x7fffffff;
#pragma unroll
            for (int j = 0; j < 32; j++) {
                if (!(excl & (1u << j))) {
                    int i = j * 256 + t;
                    if (d[j] < mv) { mv = d[j]; mi = i; }
                }
            }
        }
    }
}

// ---------------------------------------------------------------------------
// 3) group_xyz + new_xyz
// ---------------------------------------------------------------------------
__global__ void __launch_bounds__(256) gxyz_kernel(const float* __restrict__ xyz,
                                                   float* __restrict__ out) {
    int tid = blockIdx.x * 256 + threadIdx.x;
    if (tid >= BB * MM * SS) return;
    int s = tid & 31;
    int m = (tid >> 5) & (MM - 1);
    int b = tid >> 16;
    const float* p = xyz + (long)b * NN * 3;

    int i = g_nbr[tid];
    float* o = out + OFF_GXYZ + (long)tid * 3;
    o[0] = p[3 * i + 0];
    o[1] = p[3 * i + 1];
    o[2] = p[3 * i + 2];

    if (s == 0) {
        int q = g_fps[b * MM + m];
        float* o2 = out + OFF_NXYZ + (long)(b * MM + m) * 3;
        o2[0] = p[3 * q + 0];
        o2[1] = p[3 * q + 1];
        o2[2] = p[3 * q + 2];
    }
}

// ---------------------------------------------------------------------------
// 4) group_fts + new_fts_out
// ---------------------------------------------------------------------------
__global__ void __launch_bounds__(256) gfts_kernel(const float* __restrict__ fts,
                                                   float* __restrict__ out) {
    __shared__ float row[NN];
    __shared__ float ctr[512];

    const int r = blockIdx.x;       // 0..383
    const int chunk = blockIdx.y;   // 0..3
    const int b = r / (CC * DD);
    const int cd = r % (CC * DD);
    const int c = cd / DD;
    const int dd = cd % DD;
    const int t = threadIdx.x;

    const float* src = fts + ((long)(b * CC + c) * DD + dd) * NN;
#pragma unroll
    for (int k = 0; k < 8; k++) {
        int i = (k * 256 + t) * 4;
        *(float4*)&row[i] = *(const float4*)&src[i];
    }
    __syncthreads();

    const int m0 = chunk * 512;
#pragma unroll
    for (int k = 0; k < 2; k++) {
        int ml = k * 256 + t;
        ctr[ml] = row[g_fps[b * MM + m0 + ml]];
    }
    __syncthreads();

    float* o1 = out + OFF_GFTS + ((long)(b * 2 * CC + c) * DD + dd) * MM * SS;
    float* o2 = o1 + (long)CC * DD * MM * SS;
    const int* nb = g_nbr + (b * MM + m0) * SS;
    float* nfo1 = out + OFF_NFTS + ((long)(b * 2 * CC + c) * DD + dd) * MM + m0;
    float* nfo2 = nfo1 + (long)CC * DD * MM;

    for (int e = t; e < 512 * 8; e += 256) {
        int ml = e >> 3;
        int s4 = e & 7;
        int m = m0 + ml;
        int4 idx = *(const int4*)&nb[ml * SS + s4 * 4];
        float cv = ctr[ml];
        float4 v;
        v.x = __fsub_rn(row[idx.x], cv);
        v.y = __fsub_rn(row[idx.y], cv);
        v.z = __fsub_rn(row[idx.z], cv);
        v.w = __fsub_rn(row[idx.w], cv);
        long oo = (long)m * SS + s4 * 4;
        *(float4*)&o1[oo] = v;
        float4 cc4 = {cv, cv, cv, cv};
        *(float4*)&o2[oo] = cc4;
        if (s4 == 0) {
            nfo1[ml] = v.x;
            nfo2[ml] = cv;
        }
    }
}

// ---------------------------------------------------------------------------
extern "C" void kernel_launch(void* const* d_in, const int* in_sizes, int n_in,
                              void* d_out, int out_size) {
    const float* xyz = (const float*)d_in[0];
    const float* fts = (const float*)d_in[1];
    if (n_in >= 2 && in_sizes[0] != BB * NN * 3) {
        const float* tmp = xyz; xyz = fts; fts = tmp;
    }
    float* out = (float*)d_out;

    fps_kernel<<<BB, 256>>>(xyz);

    dim3 kg(MM, BB);
    knn_kernel<<<kg, 256>>>(xyz);

    gxyz_kernel<<<(BB * MM * SS + 255) / 256, 256>>>(xyz, out);

    dim3 gg(BB * CC * DD, 4);
    gfts_kernel<<<gg, 256>>>(fts, out);
}

// round 13
// speedup vs baseline: 1.3889x; 1.0442x over previous
#include <cuda_runtime.h>
#include <cuda_bf16.h>

// Problem constants
#define BB 2
#define NN 8192
#define CC 64
#define DD 3
#define MM 2048   // NPOINT
#define SS 32     // NSAMPLE

// Output layout (concatenated tuple, row-major each)
#define OFF_GXYZ 0L
#define OFF_GFTS 393216L
#define OFF_NXYZ (393216L + 50331648L)
#define OFF_NFTS (393216L + 50331648L + 12288L)

__device__ int g_fps[BB * MM];
__device__ int g_nbr[BB * MM * SS];

// packed f32x2 helpers (lane-wise IEEE rn — bit-identical to scalar)
#define MUL_F32X2(out, a, b) \
    asm("mul.rn.f32x2 %0, %1, %2;" : "=l"(out) : "l"(a), "l"(b))
#define ADD_F32X2(out, a, b) \
    asm("add.rn.f32x2 %0, %1, %2;" : "=l"(out) : "l"(a), "l"(b))
#define PACK_F32X2(out, lo, hi) \
    asm("mov.b64 %0, {%1, %2};" : "=l"(out) : "f"(lo), "f"(hi))
#define UNPACK_F32X2(lo, hi, in) \
    asm("mov.b64 {%0, %1}, %2;" : "=f"(lo), "=f"(hi) : "l"(in))

__device__ __forceinline__ unsigned redux_max_u32(unsigned v) {
    unsigned r;
    asm volatile("redux.sync.max.u32 %0, %1, 0xffffffff;" : "=r"(r) : "r"(v));
    return r;
}
__device__ __forceinline__ unsigned redux_min_u32(unsigned v) {
    unsigned r;
    asm volatile("redux.sync.min.u32 %0, %1, 0xffffffff;" : "=r"(r) : "r"(v));
    return r;
}

// strict (non-contracted) square-sum — matches reference fused square+reduce
__device__ __forceinline__ float sq3(float x, float y, float z) {
    return __fadd_rn(__fadd_rn(__fmul_rn(x, x), __fmul_rn(y, y)), __fmul_rn(z, z));
}

// ---------------------------------------------------------------------------
// 1) FPS: one block/batch, 256 threads x 32 pts. Packed-f32x2 strict
//    distances; value-only min/max inner loop. Tail: redux warp max,
//    warp-local first-index recovery (scan + redux.min), per-warp u64 key
//    (valbits<<32 | ~idx), ONE barrier, all threads max 8 keys from smem.
//    No atomics. Max key == (max value, then lowest index) since d >= 0.
// ---------------------------------------------------------------------------
__global__ void __launch_bounds__(256, 1) fps_kernel(const float* __restrict__ xyz) {
    const int b = blockIdx.x;
    const float* p = xyz + (long)b * NN * 3;
    const int tid = threadIdx.x;
    const int lane = tid & 31, warp = tid >> 5;

    // point i = j*256 + tid, j in [0,32); pairs (2k, 2k+1)
    unsigned long long px2[16], py2[16], pz2[16];
    float md[32];
#pragma unroll
    for (int k = 0; k < 16; k++) {
        int i0 = (2 * k) * 256 + tid;
        int i1 = (2 * k + 1) * 256 + tid;
        PACK_F32X2(px2[k], p[3 * i0 + 0], p[3 * i1 + 0]);
        PACK_F32X2(py2[k], p[3 * i0 + 1], p[3 * i1 + 1]);
        PACK_F32X2(pz2[k], p[3 * i0 + 2], p[3 * i1 + 2]);
        md[2 * k] = 1e10f;
        md[2 * k + 1] = 1e10f;
    }

    __shared__ __align__(16) unsigned long long s_key[8];

    if (tid == 0) g_fps[b * MM] = 0;

    float lx = p[0], ly = p[1], lz = p[2];

    for (int it = 1; it < MM; it++) {
        unsigned long long nlx2, nly2, nlz2;
        float nlx = -lx, nly = -ly, nlz = -lz;
        PACK_F32X2(nlx2, nlx, nlx);
        PACK_F32X2(nly2, nly, nly);
        PACK_F32X2(nlz2, nlz, nlz);

        float bv = -1.0f;
#pragma unroll
        for (int k = 0; k < 16; k++) {
            unsigned long long dx2, dy2, dz2, xx, yy, ss, zz, dd;
            ADD_F32X2(dx2, px2[k], nlx2);           // x - lx  (== x + (-lx))
            ADD_F32X2(dy2, py2[k], nly2);
            ADD_F32X2(dz2, pz2[k], nlz2);
            MUL_F32X2(xx, dx2, dx2);
            MUL_F32X2(yy, dy2, dy2);
            ADD_F32X2(ss, xx, yy);                  // (dx² + dy²)
            MUL_F32X2(zz, dz2, dz2);
            ADD_F32X2(dd, ss, zz);                  // + dz²
            float dlo, dhi;
            UNPACK_F32X2(dlo, dhi, dd);
            float m0 = fminf(md[2 * k], dlo);
            float m1 = fminf(md[2 * k + 1], dhi);
            md[2 * k] = m0;
            md[2 * k + 1] = m1;
            bv = fmaxf(bv, m0);
            bv = fmaxf(bv, m1);
        }

        // warp max (distances non-negative → u32 order == f32 order)
        const unsigned ub = __float_as_uint(bv);
        const unsigned wmax = redux_max_u32(ub);

        // warp-level first-index recovery (only warp-tie lanes scan)
        unsigned cand = 0xffffffffu;
        if (ub == wmax) {
            const float bmf = __uint_as_float(wmax);
            unsigned lo = 0, hi = 0;
#pragma unroll
            for (int j = 0; j < 16; j++) {
                if (md[j] == bmf)      lo |= (1u << j);
                if (md[j + 16] == bmf) hi |= (1u << j);
            }
            int jmin = lo ? (__ffs(lo) - 1) : (__ffs(hi) + 15);
            cand = jmin * 256 + tid;                 // lowest idx this thread holds
        }
        const unsigned widx = redux_min_u32(cand);   // warp's first-index winner

        if (lane == 0)
            s_key[warp] = ((unsigned long long)wmax << 32) | (unsigned)~widx;
        __syncthreads();                             // single barrier per iter

        // block winner = max of 8 keys (2x LDS.128)
        const ulonglong2 k01 = *(const ulonglong2*)&s_key[0];
        const ulonglong2 k23 = *(const ulonglong2*)&s_key[2];
        const ulonglong2 k45 = *(const ulonglong2*)&s_key[4];
        const ulonglong2 k67 = *(const ulonglong2*)&s_key[6];
        unsigned long long a0 = k01.x > k01.y ? k01.x : k01.y;
        unsigned long long a1 = k23.x > k23.y ? k23.x : k23.y;
        unsigned long long a2 = k45.x > k45.y ? k45.x : k45.y;
        unsigned long long a3 = k67.x > k67.y ? k67.x : k67.y;
        a0 = a0 > a1 ? a0 : a1;
        a2 = a2 > a3 ? a2 : a3;
        const unsigned long long fk = a0 > a2 ? a0 : a2;
        const int last = (int)~(unsigned)fk;

        if (tid == 0) g_fps[b * MM + it] = last;
        lx = p[3 * last + 0];                        // L1 broadcast
        ly = p[3 * last + 1];
        lz = p[3 * last + 2];
        // NOTE: next s_key write is >500 cyc after the barrier (behind the
        // inner loop), readers finish at bar+~60 — no double buffer needed.
    }
}

// ---------------------------------------------------------------------------
// 2) KNN (v10 — verified exact): qq/pp strict; dot fma-ascending;
//    d = qq + (pp - 2*dot); ties lower-index-first.
// ---------------------------------------------------------------------------
__global__ void __launch_bounds__(256) knn_kernel(const float* __restrict__ xyz) {
    const int m = blockIdx.x;
    const int b = blockIdx.y;
    const float* p = xyz + (long)b * NN * 3;
    const int t = threadIdx.x;

    const int qi = g_fps[b * MM + m];
    const float qx = p[3 * qi + 0], qy = p[3 * qi + 1], qz = p[3 * qi + 2];
    const float qq = sq3(qx, qy, qz);

    float d[32];
#pragma unroll
    for (int j = 0; j < 32; j++) {
        int i = j * 256 + t;
        float x = p[3 * i + 0], y = p[3 * i + 1], z = p[3 * i + 2];
        float pp = sq3(x, y, z);
        float dot = __fmaf_rn(qz, z, __fmaf_rn(qy, y, __fmul_rn(qx, x)));
        d[j] = __fadd_rn(qq, __fsub_rn(pp, __fmul_rn(2.0f, dot)));
    }

    unsigned excl = 0u;
    float mv = d[0];
    int mi = t;
#pragma unroll
    for (int j = 1; j < 32; j++) {
        int i = j * 256 + t;
        if (d[j] < mv) { mv = d[j]; mi = i; }  // strict < : lower idx wins ties
    }

    __shared__ float s_v[8];
    __shared__ int   s_i[8];
    __shared__ int   s_b;
    const int lane = t & 31, w = t >> 5;
    const int out_base = (b * MM + m) * SS;

    for (int s = 0; s < SS; s++) {
        float bv = mv;
        int bi = mi;
#pragma unroll
        for (int o = 16; o > 0; o >>= 1) {
            float ov = __shfl_down_sync(0xffffffffu, bv, o);
            int   oi = __shfl_down_sync(0xffffffffu, bi, o);
            if (ov < bv || (ov == bv && oi < bi)) { bv = ov; bi = oi; }
        }
        if (lane == 0) { s_v[w] = bv; s_i[w] = bi; }
        __syncthreads();
        if (t == 0) {
            bv = s_v[0]; bi = s_i[0];
#pragma unroll
            for (int k = 1; k < 8; k++) {
                float ov = s_v[k]; int oi = s_i[k];
                if (ov < bv || (ov == bv && oi < bi)) { bv = ov; bi = oi; }
            }
            s_b = bi;
            g_nbr[out_base + s] = bi;
        }
        __syncthreads();
        int win = s_b;
        if ((win & 255) == t) {
            excl |= 1u << (win >> 8);
            mv = 3.4e38f;
            mi = 0x7fffffff;
#pragma unroll
            for (int j = 0; j < 32; j++) {
                if (!(excl & (1u << j))) {
                    int i = j * 256 + t;
                    if (d[j] < mv) { mv = d[j]; mi = i; }
                }
            }
        }
    }
}

// ---------------------------------------------------------------------------
// 3) group_xyz + new_xyz
// ---------------------------------------------------------------------------
__global__ void __launch_bounds__(256) gxyz_kernel(const float* __restrict__ xyz,
                                                   float* __restrict__ out) {
    int tid = blockIdx.x * 256 + threadIdx.x;
    if (tid >= BB * MM * SS) return;
    int s = tid & 31;
    int m = (tid >> 5) & (MM - 1);
    int b = tid >> 16;
    const float* p = xyz + (long)b * NN * 3;

    int i = g_nbr[tid];
    float* o = out + OFF_GXYZ + (long)tid * 3;
    o[0] = p[3 * i + 0];
    o[1] = p[3 * i + 1];
    o[2] = p[3 * i + 2];

    if (s == 0) {
        int q = g_fps[b * MM + m];
        float* o2 = out + OFF_NXYZ + (long)(b * MM + m) * 3;
        o2[0] = p[3 * q + 0];
        o2[1] = p[3 * q + 1];
        o2[2] = p[3 * q + 2];
    }
}

// ---------------------------------------------------------------------------
// 4) group_fts + new_fts_out
// ---------------------------------------------------------------------------
__global__ void __launch_bounds__(256) gfts_kernel(const float* __restrict__ fts,
                                                   float* __restrict__ out) {
    __shared__ float row[NN];
    __shared__ float ctr[512];

    const int r = blockIdx.x;       // 0..383
    const int chunk = blockIdx.y;   // 0..3
    const int b = r / (CC * DD);
    const int cd = r % (CC * DD);
    const int c = cd / DD;
    const int dd = cd % DD;
    const int t = threadIdx.x;

    const float* src = fts + ((long)(b * CC + c) * DD + dd) * NN;
#pragma unroll
    for (int k = 0; k < 8; k++) {
        int i = (k * 256 + t) * 4;
        *(float4*)&row[i] = *(const float4*)&src[i];
    }
    __syncthreads();

    const int m0 = chunk * 512;
#pragma unroll
    for (int k = 0; k < 2; k++) {
        int ml = k * 256 + t;
        ctr[ml] = row[g_fps[b * MM + m0 + ml]];
    }
    __syncthreads();

    float* o1 = out + OFF_GFTS + ((long)(b * 2 * CC + c) * DD + dd) * MM * SS;
    float* o2 = o1 + (long)CC * DD * MM * SS;
    const int* nb = g_nbr + (b * MM + m0) * SS;
    float* nfo1 = out + OFF_NFTS + ((long)(b * 2 * CC + c) * DD + dd) * MM + m0;
    float* nfo2 = nfo1 + (long)CC * DD * MM;

    for (int e = t; e < 512 * 8; e += 256) {
        int ml = e >> 3;
        int s4 = e & 7;
        int m = m0 + ml;
        int4 idx = *(const int4*)&nb[ml * SS + s4 * 4];
        float cv = ctr[ml];
        float4 v;
        v.x = __fsub_rn(row[idx.x], cv);
        v.y = __fsub_rn(row[idx.y], cv);
        v.z = __fsub_rn(row[idx.z], cv);
        v.w = __fsub_rn(row[idx.w], cv);
        long oo = (long)m * SS + s4 * 4;
        *(float4*)&o1[oo] = v;
        float4 cc4 = {cv, cv, cv, cv};
        *(float4*)&o2[oo] = cc4;
        if (s4 == 0) {
            nfo1[ml] = v.x;
            nfo2[ml] = cv;
        }
    }
}

// ---------------------------------------------------------------------------
extern "C" void kernel_launch(void* const* d_in, const int* in_sizes, int n_in,
                              void* d_out, int out_size) {
    const float* xyz = (const float*)d_in[0];
    const float* fts = (const float*)d_in[1];
    if (n_in >= 2 && in_sizes[0] != BB * NN * 3) {
        const float* tmp = xyz; xyz = fts; fts = tmp;
    }
    float* out = (float*)d_out;

    fps_kernel<<<BB, 256>>>(xyz);

    dim3 kg(MM, BB);
    knn_kernel<<<kg, 256>>>(xyz);

    gxyz_kernel<<<(BB * MM * SS + 255) / 256, 256>>>(xyz, out);

    dim3 gg(BB * CC * DD, 4);
    gfts_kernel<<<gg, 256>>>(fts, out);
}

// round 14
// speedup vs baseline: 1.6348x; 1.1770x over previous
#include <cuda_runtime.h>
#include <cuda_bf16.h>

// Problem constants
#define BB 2
#define NN 8192
#define CC 64
#define DD 3
#define MM 2048   // NPOINT
#define SS 32     // NSAMPLE

// Output layout (concatenated tuple, row-major each)
#define OFF_GXYZ 0L
#define OFF_GFTS 393216L
#define OFF_NXYZ (393216L + 50331648L)
#define OFF_NFTS (393216L + 50331648L + 12288L)

__device__ int g_fps[BB * MM];
__device__ int g_nbr[BB * MM * SS];

// packed f32x2 helpers (lane-wise IEEE rn — bit-identical to scalar)
#define MUL_F32X2(out, a, b) \
    asm("mul.rn.f32x2 %0, %1, %2;" : "=l"(out) : "l"(a), "l"(b))
#define ADD_F32X2(out, a, b) \
    asm("add.rn.f32x2 %0, %1, %2;" : "=l"(out) : "l"(a), "l"(b))
#define PACK_F32X2(out, lo, hi) \
    asm("mov.b64 %0, {%1, %2};" : "=l"(out) : "f"(lo), "f"(hi))
#define UNPACK_F32X2(lo, hi, in) \
    asm("mov.b64 {%0, %1}, %2;" : "=f"(lo), "=f"(hi) : "l"(in))

__device__ __forceinline__ unsigned redux_max_u32(unsigned v) {
    unsigned r;
    asm volatile("redux.sync.max.u32 %0, %1, 0xffffffff;" : "=r"(r) : "r"(v));
    return r;
}

// strict (non-contracted) square-sum — matches reference fused square+reduce
__device__ __forceinline__ float sq3(float x, float y, float z) {
    return __fadd_rn(__fadd_rn(__fmul_rn(x, x), __fmul_rn(y, y)), __fmul_rn(z, z));
}

// ---------------------------------------------------------------------------
// 1) FPS: one block/batch, 256 threads x 32 pts (R10 skeleton).
//    Packed-f32x2 strict distances; value-only min/max inner loop.
//    Tail: redux.sync warp max (u32 order == f32 order for d >= 0),
//    per-warp smem value, block max via 2xLDS.128, winner gated on BLOCK
//    max does mask+ffs first-index scan + atomicMin, double-buffered slots.
// ---------------------------------------------------------------------------
__global__ void __launch_bounds__(256, 1) fps_kernel(const float* __restrict__ xyz) {
    const int b = blockIdx.x;
    const float* p = xyz + (long)b * NN * 3;
    const int tid = threadIdx.x;
    const int lane = tid & 31, warp = tid >> 5;

    // point i = j*256 + tid, j in [0,32); pairs (2k, 2k+1)
    unsigned long long px2[16], py2[16], pz2[16];
    float md[32];
#pragma unroll
    for (int k = 0; k < 16; k++) {
        int i0 = (2 * k) * 256 + tid;
        int i1 = (2 * k + 1) * 256 + tid;
        PACK_F32X2(px2[k], p[3 * i0 + 0], p[3 * i1 + 0]);
        PACK_F32X2(py2[k], p[3 * i0 + 1], p[3 * i1 + 1]);
        PACK_F32X2(pz2[k], p[3 * i0 + 2], p[3 * i1 + 2]);
        md[2 * k] = 1e10f;
        md[2 * k + 1] = 1e10f;
    }

    __shared__ __align__(16) unsigned s_val[8];
    __shared__ int s_idx[2];

    if (tid == 0) {
        g_fps[b * MM] = 0;
        s_idx[0] = 0x7fffffff;
        s_idx[1] = 0x7fffffff;
    }
    __syncthreads();

    float lx = p[0], ly = p[1], lz = p[2];

    for (int it = 1; it < MM; it++) {
        unsigned long long nlx2, nly2, nlz2;
        float nlx = -lx, nly = -ly, nlz = -lz;
        PACK_F32X2(nlx2, nlx, nlx);
        PACK_F32X2(nly2, nly, nly);
        PACK_F32X2(nlz2, nlz, nlz);

        float bv = -1.0f;
#pragma unroll
        for (int k = 0; k < 16; k++) {
            unsigned long long dx2, dy2, dz2, xx, yy, ss, zz, dd;
            ADD_F32X2(dx2, px2[k], nlx2);           // x - lx  (== x + (-lx))
            ADD_F32X2(dy2, py2[k], nly2);
            ADD_F32X2(dz2, pz2[k], nlz2);
            MUL_F32X2(xx, dx2, dx2);
            MUL_F32X2(yy, dy2, dy2);
            ADD_F32X2(ss, xx, yy);                  // (dx² + dy²)
            MUL_F32X2(zz, dz2, dz2);
            ADD_F32X2(dd, ss, zz);                  // + dz²
            float dlo, dhi;
            UNPACK_F32X2(dlo, dhi, dd);
            float m0 = fminf(md[2 * k], dlo);
            float m1 = fminf(md[2 * k + 1], dhi);
            md[2 * k] = m0;
            md[2 * k + 1] = m1;
            bv = fmaxf(bv, m0);
            bv = fmaxf(bv, m1);
        }

        // warp max via redux (distances non-negative → u32 order == f32 order)
        const unsigned ub = __float_as_uint(bv);
        const unsigned wmax = redux_max_u32(ub);
        if (lane == 0) s_val[warp] = wmax;
        __syncthreads();                             // bar A

        // block max: 2x LDS.128 + 7 u32 max
        const uint4 v0 = *(const uint4*)&s_val[0];
        const uint4 v1 = *(const uint4*)&s_val[4];
        unsigned b0 = v0.x > v0.y ? v0.x : v0.y;
        unsigned b1 = v0.z > v0.w ? v0.z : v0.w;
        unsigned b2 = v1.x > v1.y ? v1.x : v1.y;
        unsigned b3 = v1.z > v1.w ? v1.z : v1.w;
        b0 = b0 > b1 ? b0 : b1;
        b2 = b2 > b3 ? b2 : b3;
        const unsigned bm = b0 > b2 ? b0 : b2;

        const int slot = it & 1;
        if (ub == bm) {
            // only block-max holders (typically 1 thread) pay the scan
            const float bmf = __uint_as_float(bm);
            unsigned lo = 0, hi = 0;
#pragma unroll
            for (int j = 0; j < 16; j++) {
                if (md[j] == bmf)      lo |= (1u << j);
                if (md[j + 16] == bmf) hi |= (1u << j);
            }
            int jmin = lo ? (__ffs(lo) - 1) : (__ffs(hi) + 15);
            atomicMin(&s_idx[slot], jmin * 256 + tid);
        }
        if (tid == 0) s_idx[slot ^ 1] = 0x7fffffff;  // reset next slot
        __syncthreads();                             // bar B

        const int last = s_idx[slot];
        if (tid == 0) g_fps[b * MM + it] = last;
        lx = p[3 * last + 0];                        // L1 broadcast
        ly = p[3 * last + 1];
        lz = p[3 * last + 2];
    }
}

// ---------------------------------------------------------------------------
// 2) KNN (v10 — verified exact): qq/pp strict; dot fma-ascending;
//    d = qq + (pp - 2*dot); ties lower-index-first.
// ---------------------------------------------------------------------------
__global__ void __launch_bounds__(256) knn_kernel(const float* __restrict__ xyz) {
    const int m = blockIdx.x;
    const int b = blockIdx.y;
    const float* p = xyz + (long)b * NN * 3;
    const int t = threadIdx.x;

    const int qi = g_fps[b * MM + m];
    const float qx = p[3 * qi + 0], qy = p[3 * qi + 1], qz = p[3 * qi + 2];
    const float qq = sq3(qx, qy, qz);

    float d[32];
#pragma unroll
    for (int j = 0; j < 32; j++) {
        int i = j * 256 + t;
        float x = p[3 * i + 0], y = p[3 * i + 1], z = p[3 * i + 2];
        float pp = sq3(x, y, z);
        float dot = __fmaf_rn(qz, z, __fmaf_rn(qy, y, __fmul_rn(qx, x)));
        d[j] = __fadd_rn(qq, __fsub_rn(pp, __fmul_rn(2.0f, dot)));
    }

    unsigned excl = 0u;
    float mv = d[0];
    int mi = t;
#pragma unroll
    for (int j = 1; j < 32; j++) {
        int i = j * 256 + t;
        if (d[j] < mv) { mv = d[j]; mi = i; }  // strict < : lower idx wins ties
    }

    __shared__ float s_v[8];
    __shared__ int   s_i[8];
    __shared__ int   s_b;
    const int lane = t & 31, w = t >> 5;
    const int out_base = (b * MM + m) * SS;

    for (int s = 0; s < SS; s++) {
        float bv = mv;
        int bi = mi;
#pragma unroll
        for (int o = 16; o > 0; o >>= 1) {
            float ov = __shfl_down_sync(0xffffffffu, bv, o);
            int   oi = __shfl_down_sync(0xffffffffu, bi, o);
            if (ov < bv || (ov == bv && oi < bi)) { bv = ov; bi = oi; }
        }
        if (lane == 0) { s_v[w] = bv; s_i[w] = bi; }
        __syncthreads();
        if (t == 0) {
            bv = s_v[0]; bi = s_i[0];
#pragma unroll
            for (int k = 1; k < 8; k++) {
                float ov = s_v[k]; int oi = s_i[k];
                if (ov < bv || (ov == bv && oi < bi)) { bv = ov; bi = oi; }
            }
            s_b = bi;
            g_nbr[out_base + s] = bi;
        }
        __syncthreads();
        int win = s_b;
        if ((win & 255) == t) {
            excl |= 1u << (win >> 8);
            mv = 3.4e38f;
            mi = 0x7fffffff;
#pragma unroll
            for (int j = 0; j < 32; j++) {
                if (!(excl & (1u << j))) {
                    int i = j * 256 + t;
                    if (d[j] < mv) { mv = d[j]; mi = i; }
                }
            }
        }
    }
}

// ---------------------------------------------------------------------------
// 3) group_xyz + new_xyz
// ---------------------------------------------------------------------------
__global__ void __launch_bounds__(256) gxyz_kernel(const float* __restrict__ xyz,
                                                   float* __restrict__ out) {
    int tid = blockIdx.x * 256 + threadIdx.x;
    if (tid >= BB * MM * SS) return;
    int s = tid & 31;
    int m = (tid >> 5) & (MM - 1);
    int b = tid >> 16;
    const float* p = xyz + (long)b * NN * 3;

    int i = g_nbr[tid];
    float* o = out + OFF_GXYZ + (long)tid * 3;
    o[0] = p[3 * i + 0];
    o[1] = p[3 * i + 1];
    o[2] = p[3 * i + 2];

    if (s == 0) {
        int q = g_fps[b * MM + m];
        float* o2 = out + OFF_NXYZ + (long)(b * MM + m) * 3;
        o2[0] = p[3 * q + 0];
        o2[1] = p[3 * q + 1];
        o2[2] = p[3 * q + 2];
    }
}

// ---------------------------------------------------------------------------
// 4) group_fts + new_fts_out
// ---------------------------------------------------------------------------
__global__ void __launch_bounds__(256) gfts_kernel(const float* __restrict__ fts,
                                                   float* __restrict__ out) {
    __shared__ float row[NN];
    __shared__ float ctr[512];

    const int r = blockIdx.x;       // 0..383
    const int chunk = blockIdx.y;   // 0..3
    const int b = r / (CC * DD);
    const int cd = r % (CC * DD);
    const int c = cd / DD;
    const int dd = cd % DD;
    const int t = threadIdx.x;

    const float* src = fts + ((long)(b * CC + c) * DD + dd) * NN;
#pragma unroll
    for (int k = 0; k < 8; k++) {
        int i = (k * 256 + t) * 4;
        *(float4*)&row[i] = *(const float4*)&src[i];
    }
    __syncthreads();

    const int m0 = chunk * 512;
#pragma unroll
    for (int k = 0; k < 2; k++) {
        int ml = k * 256 + t;
        ctr[ml] = row[g_fps[b * MM + m0 + ml]];
    }
    __syncthreads();

    float* o1 = out + OFF_GFTS + ((long)(b * 2 * CC + c) * DD + dd) * MM * SS;
    float* o2 = o1 + (long)CC * DD * MM * SS;
    const int* nb = g_nbr + (b * MM + m0) * SS;
    float* nfo1 = out + OFF_NFTS + ((long)(b * 2 * CC + c) * DD + dd) * MM + m0;
    float* nfo2 = nfo1 + (long)CC * DD * MM;

    for (int e = t; e < 512 * 8; e += 256) {
        int ml = e >> 3;
        int s4 = e & 7;
        int m = m0 + ml;
        int4 idx = *(const int4*)&nb[ml * SS + s4 * 4];
        float cv = ctr[ml];
        float4 v;
        v.x = __fsub_rn(row[idx.x], cv);
        v.y = __fsub_rn(row[idx.y], cv);
        v.z = __fsub_rn(row[idx.z], cv);
        v.w = __fsub_rn(row[idx.w], cv);
        long oo = (long)m * SS + s4 * 4;
        *(float4*)&o1[oo] = v;
        float4 cc4 = {cv, cv, cv, cv};
        *(float4*)&o2[oo] = cc4;
        if (s4 == 0) {
            nfo1[ml] = v.x;
            nfo2[ml] = cv;
        }
    }
}

// ---------------------------------------------------------------------------
extern "C" void kernel_launch(void* const* d_in, const int* in_sizes, int n_in,
                              void* d_out, int out_size) {
    const float* xyz = (const float*)d_in[0];
    const float* fts = (const float*)d_in[1];
    if (n_in >= 2 && in_sizes[0] != BB * NN * 3) {
        const float* tmp = xyz; xyz = fts; fts = tmp;
    }
    float* out = (float*)d_out;

    fps_kernel<<<BB, 256>>>(xyz);

    dim3 kg(MM, BB);
    knn_kernel<<<kg, 256>>>(xyz);

    gxyz_kernel<<<(BB * MM * SS + 255) / 256, 256>>>(xyz, out);

    dim3 gg(BB * CC * DD, 4);
    gfts_kernel<<<gg, 256>>>(fts, out);
}

// round 15
// speedup vs baseline: 1.7942x; 1.0975x over previous
#include <cuda_runtime.h>
#include <cuda_bf16.h>

// Problem constants
#define BB 2
#define NN 8192
#define CC 64
#define DD 3
#define MM 2048   // NPOINT
#define SS 32     // NSAMPLE

// Output layout (concatenated tuple, row-major each)
#define OFF_GXYZ 0L
#define OFF_GFTS 393216L
#define OFF_NXYZ (393216L + 50331648L)
#define OFF_NFTS (393216L + 50331648L + 12288L)

__device__ int g_fps[BB * MM];     // sentinel -1, written progressively by FPS
__device__ int g_nbr[BB * MM * SS];
__device__ int g_flag[BB * MM];    // per-query KNN done flag
__device__ int g_cnt[BB * 4];      // per-(b,chunk) KNN completion counter

// packed f32x2 helpers (lane-wise IEEE rn — bit-identical to scalar)
#define MUL_F32X2(out, a, b) \
    asm("mul.rn.f32x2 %0, %1, %2;" : "=l"(out) : "l"(a), "l"(b))
#define ADD_F32X2(out, a, b) \
    asm("add.rn.f32x2 %0, %1, %2;" : "=l"(out) : "l"(a), "l"(b))
#define PACK_F32X2(out, lo, hi) \
    asm("mov.b64 %0, {%1, %2};" : "=l"(out) : "f"(lo), "f"(hi))
#define UNPACK_F32X2(lo, hi, in) \
    asm("mov.b64 {%0, %1}, %2;" : "=f"(lo), "=f"(hi) : "l"(in))

__device__ __forceinline__ unsigned redux_max_u32(unsigned v) {
    unsigned r;
    asm volatile("redux.sync.max.u32 %0, %1, 0xffffffff;" : "=r"(r) : "r"(v));
    return r;
}

// strict (non-contracted) square-sum — matches reference fused square+reduce
__device__ __forceinline__ float sq3(float x, float y, float z) {
    return __fadd_rn(__fadd_rn(__fmul_rn(x, x), __fmul_rn(y, y)), __fmul_rn(z, z));
}

// ---------------------------------------------------------------------------
// init: sentinels/flags/counters (must run each graph replay)
// ---------------------------------------------------------------------------
__global__ void init_kernel() {
    int i = blockIdx.x * 256 + threadIdx.x;
    if (i < BB * MM) {
        g_fps[i] = -1;
        g_flag[i] = 0;
    }
    if (i < BB * 4) g_cnt[i] = 0;
}

// ---------------------------------------------------------------------------
// Mega-kernel: block role by blockIdx.x
//   [0,2)           FPS (one per batch)               — wave-1 resident
//   [2,4098)        KNN (bid-2 = m*2+b)               — polls g_fps[m]
//   [4098,4610)     gxyz (512)                        — polls g_flag
//   [4610,6146)     gfts (1536: r + 384*chunk)        — polls g_cnt
// Dependencies flow strictly low-bid -> high-bid; FPS always resident.
// ---------------------------------------------------------------------------
#define BID_KNN   2
#define BID_GXYZ  4098
#define BID_GFTS  4610
#define BID_TOTAL 6146

__global__ void __launch_bounds__(256, 1)
mega_kernel(const float* __restrict__ xyz, const float* __restrict__ fts,
            float* __restrict__ out) {
    __shared__ float row[NN];          // gfts
    __shared__ float ctr[512];         // gfts
    __shared__ __align__(16) unsigned s_val[8];  // fps
    __shared__ int s_idx[2];           // fps
    __shared__ float s_v[8];           // knn
    __shared__ int   s_i[8];           // knn
    __shared__ int   s_b;              // knn

    const int bid = blockIdx.x;
    const int tid = threadIdx.x;

    // =====================================================================
    if (bid < BID_KNN) {
        // ------------------------------ FPS (R14 body, volatile publishes)
        const int b = bid;
        const float* p = xyz + (long)b * NN * 3;
        const int lane = tid & 31, warp = tid >> 5;
        volatile int* vfps = g_fps;

        unsigned long long px2[16], py2[16], pz2[16];
        float md[32];
#pragma unroll
        for (int k = 0; k < 16; k++) {
            int i0 = (2 * k) * 256 + tid;
            int i1 = (2 * k + 1) * 256 + tid;
            PACK_F32X2(px2[k], p[3 * i0 + 0], p[3 * i1 + 0]);
            PACK_F32X2(py2[k], p[3 * i0 + 1], p[3 * i1 + 1]);
            PACK_F32X2(pz2[k], p[3 * i0 + 2], p[3 * i1 + 2]);
            md[2 * k] = 1e10f;
            md[2 * k + 1] = 1e10f;
        }

        if (tid == 0) {
            vfps[b * MM] = 0;
            s_idx[0] = 0x7fffffff;
            s_idx[1] = 0x7fffffff;
        }
        __syncthreads();

        float lx = p[0], ly = p[1], lz = p[2];

        for (int it = 1; it < MM; it++) {
            unsigned long long nlx2, nly2, nlz2;
            float nlx = -lx, nly = -ly, nlz = -lz;
            PACK_F32X2(nlx2, nlx, nlx);
            PACK_F32X2(nly2, nly, nly);
            PACK_F32X2(nlz2, nlz, nlz);

            float bv = -1.0f;
#pragma unroll
            for (int k = 0; k < 16; k++) {
                unsigned long long dx2, dy2, dz2, xx, yy, ss, zz, dd;
                ADD_F32X2(dx2, px2[k], nlx2);
                ADD_F32X2(dy2, py2[k], nly2);
                ADD_F32X2(dz2, pz2[k], nlz2);
                MUL_F32X2(xx, dx2, dx2);
                MUL_F32X2(yy, dy2, dy2);
                ADD_F32X2(ss, xx, yy);
                MUL_F32X2(zz, dz2, dz2);
                ADD_F32X2(dd, ss, zz);
                float dlo, dhi;
                UNPACK_F32X2(dlo, dhi, dd);
                float m0 = fminf(md[2 * k], dlo);
                float m1 = fminf(md[2 * k + 1], dhi);
                md[2 * k] = m0;
                md[2 * k + 1] = m1;
                bv = fmaxf(bv, m0);
                bv = fmaxf(bv, m1);
            }

            const unsigned ub = __float_as_uint(bv);
            const unsigned wmax = redux_max_u32(ub);
            if (lane == 0) s_val[warp] = wmax;
            __syncthreads();

            const uint4 v0 = *(const uint4*)&s_val[0];
            const uint4 v1 = *(const uint4*)&s_val[4];
            unsigned b0 = v0.x > v0.y ? v0.x : v0.y;
            unsigned b1 = v0.z > v0.w ? v0.z : v0.w;
            unsigned b2 = v1.x > v1.y ? v1.x : v1.y;
            unsigned b3 = v1.z > v1.w ? v1.z : v1.w;
            b0 = b0 > b1 ? b0 : b1;
            b2 = b2 > b3 ? b2 : b3;
            const unsigned bm = b0 > b2 ? b0 : b2;

            const int slot = it & 1;
            if (ub == bm) {
                const float bmf = __uint_as_float(bm);
                unsigned lo = 0, hi = 0;
#pragma unroll
                for (int j = 0; j < 16; j++) {
                    if (md[j] == bmf)      lo |= (1u << j);
                    if (md[j + 16] == bmf) hi |= (1u << j);
                }
                int jmin = lo ? (__ffs(lo) - 1) : (__ffs(hi) + 15);
                atomicMin(&s_idx[slot], jmin * 256 + tid);
            }
            if (tid == 0) s_idx[slot ^ 1] = 0x7fffffff;
            __syncthreads();

            const int last = s_idx[slot];
            if (tid == 0) vfps[b * MM + it] = last;   // publish progressively
            lx = p[3 * last + 0];
            ly = p[3 * last + 1];
            lz = p[3 * last + 2];
        }
    }
    // =====================================================================
    else if (bid < BID_GXYZ) {
        // ------------------------------ KNN (v10 exact), polls g_fps[m]
        const int bid2 = bid - BID_KNN;
        const int m = bid2 >> 1;
        const int b = bid2 & 1;
        const float* p = xyz + (long)b * NN * 3;
        const int t = tid;

        int qi;
        if (t == 0) {
            volatile int* vfps = g_fps;
            while ((qi = vfps[b * MM + m]) < 0) { }
            s_b = qi;
        }
        __syncthreads();
        qi = s_b;

        const float qx = p[3 * qi + 0], qy = p[3 * qi + 1], qz = p[3 * qi + 2];
        const float qq = sq3(qx, qy, qz);

        float d[32];
#pragma unroll
        for (int j = 0; j < 32; j++) {
            int i = j * 256 + t;
            float x = p[3 * i + 0], y = p[3 * i + 1], z = p[3 * i + 2];
            float pp = sq3(x, y, z);
            float dot = __fmaf_rn(qz, z, __fmaf_rn(qy, y, __fmul_rn(qx, x)));
            d[j] = __fadd_rn(qq, __fsub_rn(pp, __fmul_rn(2.0f, dot)));
        }

        unsigned excl = 0u;
        float mv = d[0];
        int mi = t;
#pragma unroll
        for (int j = 1; j < 32; j++) {
            int i = j * 256 + t;
            if (d[j] < mv) { mv = d[j]; mi = i; }
        }

        const int lane = t & 31, w = t >> 5;
        const int out_base = (b * MM + m) * SS;

        for (int s = 0; s < SS; s++) {
            float bv = mv;
            int bi = mi;
#pragma unroll
            for (int o = 16; o > 0; o >>= 1) {
                float ov = __shfl_down_sync(0xffffffffu, bv, o);
                int   oi = __shfl_down_sync(0xffffffffu, bi, o);
                if (ov < bv || (ov == bv && oi < bi)) { bv = ov; bi = oi; }
            }
            if (lane == 0) { s_v[w] = bv; s_i[w] = bi; }
            __syncthreads();
            if (t == 0) {
                bv = s_v[0]; bi = s_i[0];
#pragma unroll
                for (int k = 1; k < 8; k++) {
                    float ov = s_v[k]; int oi = s_i[k];
                    if (ov < bv || (ov == bv && oi < bi)) { bv = ov; bi = oi; }
                }
                s_b = bi;
                g_nbr[out_base + s] = bi;
            }
            __syncthreads();
            int win = s_b;
            if ((win & 255) == t) {
                excl |= 1u << (win >> 8);
                mv = 3.4e38f;
                mi = 0x7fffffff;
#pragma unroll
                for (int j = 0; j < 32; j++) {
                    if (!(excl & (1u << j))) {
                        int i = j * 256 + t;
                        if (d[j] < mv) { mv = d[j]; mi = i; }
                    }
                }
            }
        }

        __syncthreads();
        if (t == 0) {
            __threadfence();                               // g_nbr visible
            ((volatile int*)g_flag)[b * MM + m] = 1;       // per-m flag
            atomicAdd(&g_cnt[b * 4 + (m >> 9)], 1);        // per-chunk counter
        }
    }
    // =====================================================================
    else if (bid < BID_GFTS) {
        // ------------------------------ gxyz + new_xyz, polls 8 flags
        const int bid3 = bid - BID_GXYZ;
        const int gtid = bid3 * 256 + tid;   // over B*M*S = 131072
        const int s = gtid & 31;
        const int m = (gtid >> 5) & (MM - 1);
        const int b = gtid >> 16;

        // this block covers 8 consecutive m for one b
        if (tid < 8) {
            const int m0 = ((bid3 * 256) >> 5) & (MM - 1);
            const int bb = (bid3 * 256) >> 16;
            volatile int* vf = g_flag;
            while (vf[bb * MM + m0 + tid] == 0) { }
        }
        __syncthreads();

        const float* p = xyz + (long)b * NN * 3;
        int i = g_nbr[gtid];
        float* o = out + OFF_GXYZ + (long)gtid * 3;
        o[0] = p[3 * i + 0];
        o[1] = p[3 * i + 1];
        o[2] = p[3 * i + 2];

        if (s == 0) {
            int q = g_fps[b * MM + m];
            float* o2 = out + OFF_NXYZ + (long)(b * MM + m) * 3;
            o2[0] = p[3 * q + 0];
            o2[1] = p[3 * q + 1];
            o2[2] = p[3 * q + 2];
        }
    }
    // =====================================================================
    else {
        // ------------------------------ gfts + new_fts, polls chunk counter
        const int bid4 = bid - BID_GFTS;
        const int r = bid4 % 384;
        const int chunk = bid4 / 384;
        const int b = r / (CC * DD);
        const int cd = r % (CC * DD);
        const int c = cd / DD;
        const int dd = cd % DD;
        const int t = tid;

        if (t == 0) {
            volatile int* vc = g_cnt;
            while (vc[b * 4 + chunk] < 512) { }
        }
        __syncthreads();

        const float* src = fts + ((long)(b * CC + c) * DD + dd) * NN;
#pragma unroll
        for (int k = 0; k < 8; k++) {
            int i = (k * 256 + t) * 4;
            *(float4*)&row[i] = *(const float4*)&src[i];
        }
        __syncthreads();

        const int m0 = chunk * 512;
#pragma unroll
        for (int k = 0; k < 2; k++) {
            int ml = k * 256 + t;
            ctr[ml] = row[g_fps[b * MM + m0 + ml]];
        }
        __syncthreads();

        float* o1 = out + OFF_GFTS + ((long)(b * 2 * CC + c) * DD + dd) * MM * SS;
        float* o2 = o1 + (long)CC * DD * MM * SS;
        const int* nb = g_nbr + (b * MM + m0) * SS;
        float* nfo1 = out + OFF_NFTS + ((long)(b * 2 * CC + c) * DD + dd) * MM + m0;
        float* nfo2 = nfo1 + (long)CC * DD * MM;

        for (int e = t; e < 512 * 8; e += 256) {
            int ml = e >> 3;
            int s4 = e & 7;
            int m = m0 + ml;
            int4 idx = *(const int4*)&nb[ml * SS + s4 * 4];
            float cv = ctr[ml];
            float4 v;
            v.x = __fsub_rn(row[idx.x], cv);
            v.y = __fsub_rn(row[idx.y], cv);
            v.z = __fsub_rn(row[idx.z], cv);
            v.w = __fsub_rn(row[idx.w], cv);
            long oo = (long)m * SS + s4 * 4;
            *(float4*)&o1[oo] = v;
            float4 cc4 = {cv, cv, cv, cv};
            *(float4*)&o2[oo] = cc4;
            if (s4 == 0) {
                nfo1[ml] = v.x;
                nfo2[ml] = cv;
            }
        }
    }
}

// ---------------------------------------------------------------------------
extern "C" void kernel_launch(void* const* d_in, const int* in_sizes, int n_in,
                              void* d_out, int out_size) {
    const float* xyz = (const float*)d_in[0];
    const float* fts = (const float*)d_in[1];
    if (n_in >= 2 && in_sizes[0] != BB * NN * 3) {
        const float* tmp = xyz; xyz = fts; fts = tmp;
    }
    float* out = (float*)d_out;

    init_kernel<<<(BB * MM + 255) / 256, 256>>>();
    mega_kernel<<<BID_TOTAL, 256>>>(xyz, fts, out);
}